// round 2
// baseline (speedup 1.0000x reference)
#include <cuda_runtime.h>
#include <cstdint>

#define NB 2
#define NN 2048
#define NH 4
#define ND 32
#define NF 128
#define EPSV 1e-5f

// Scratch (device globals — no allocation allowed)
__device__ float g_h[NB*NN*NF];                 // h = x @ w^T   [b][n][o]
__device__ float g_V[NB*NN*NF];                 // permuted V    [b][j][d][h]
__device__ float g_EI[NB*NN*NH];                // ei per (b,n,h)
__device__ float g_EJ[NB*NN*NH];                // ej per (b,n,h)
__device__ unsigned g_adjbits[NN*(NN/32)];      // adj bitmask [i][jword]
__device__ float g_part[2*NB*NN*NF];            // partial AV   [jh][row][o]
__device__ float g_psum[2*NB*NN*NH];            // partial softmax sums [jh][row][h]

// ---------------------------------------------------------------------------
// Prep: h = x@w^T, ei/ej, and the scrambled V gather ([b][j][d][h] layout)
// 16 rows per block, 256 threads.
// ---------------------------------------------------------------------------
__global__ __launch_bounds__(256) void prep_kernel(const float* __restrict__ x,
                                                   const float* __restrict__ w,
                                                   const float* __restrict__ a) {
    __shared__ float w_s[64*129];   // [k][o] padded stride 129 (conflict-free)
    __shared__ float x_s[16*64];
    __shared__ float h_s[16*128];
    __shared__ float a_s[NH*64];
    int t = threadIdx.x;
    int n0 = blockIdx.x * 16;       // global row base over B*N = 4096

    for (int idx = t; idx < 128*64; idx += 256) {
        int o = idx >> 6, k = idx & 63;
        w_s[k*129 + o] = w[idx];
    }
    for (int idx = t; idx < 16*64; idx += 256) x_s[idx] = x[n0*64 + idx];
    if (t < NH*64) a_s[t] = a[t];
    __syncthreads();

    {   // GEMM: thread computes 8 outputs for one row
        int r = t >> 4, og = t & 15;
        float acc[8];
        #pragma unroll
        for (int u = 0; u < 8; u++) acc[u] = 0.f;
        #pragma unroll
        for (int k = 0; k < 64; k++) {
            float xv = x_s[r*64 + k];
            #pragma unroll
            for (int u = 0; u < 8; u++)
                acc[u] = fmaf(xv, w_s[k*129 + og + u*16], acc[u]);
        }
        #pragma unroll
        for (int u = 0; u < 8; u++) {
            int o = og + u*16;
            h_s[r*128 + o] = acc[u];
            g_h[(size_t)(n0 + r)*128 + o] = acc[u];
        }
    }
    __syncthreads();

    // ei / ej
    if (t < 64) {
        int r = t >> 2, hh = t & 3;
        float ei = 0.f, ej = 0.f;
        #pragma unroll
        for (int d = 0; d < 32; d++) {
            float hv = h_s[r*128 + hh*32 + d];
            ei = fmaf(hv, a_s[hh*64 + d], ei);
            ej = fmaf(hv, a_s[hh*64 + 32 + d], ej);
        }
        int ng = n0 + r;
        g_EI[ng*4 + hh] = ei;
        g_EJ[ng*4 + hh] = ej;
    }
    // V scatter: v[b, g>>2, g&3, d] = h[b, n, ho, d] with g = ho*2048 + n
    {
        int r = t >> 4, dd = (t & 15) * 2;
        int ng = n0 + r;
        int b = ng >> 11, n = ng & 2047;
        #pragma unroll
        for (int ho = 0; ho < 4; ho++) {
            int g = ho*2048 + n;
            int j = g >> 2, hn = g & 3;
            int base = (b*2048 + j)*128 + hn;
            g_V[base + dd*4]       = h_s[r*128 + ho*32 + dd];
            g_V[base + (dd+1)*4]   = h_s[r*128 + ho*32 + dd + 1];
        }
    }
}

// ---------------------------------------------------------------------------
// adj -> bitmask (512 KB, L2 resident)
// ---------------------------------------------------------------------------
__global__ __launch_bounds__(256) void adjbits_kernel(const int* __restrict__ adj) {
    int w = threadIdx.x >> 5, lane = threadIdx.x & 31;
    int warp_g = blockIdx.x * 8 + w;
    #pragma unroll
    for (int u = 0; u < 8; u++) {
        int wi = warp_g * 8 + u;           // 0..131071
        int i = wi >> 6, c = wi & 63;
        int v = adj[(size_t)i*2048 + c*32 + lane];
        unsigned m = __ballot_sync(0xFFFFFFFFu, v != 0);
        if (lane == 0) g_adjbits[wi] = m;
    }
}

// ---------------------------------------------------------------------------
// Main attention (partial over half the j-range).
// Grid (128, 2): blockIdx.x = 32-row tile over B*N rows, blockIdx.y = j half.
// 128 threads = 4 warps; warp handles 8 i-rows; lane = d.
// acc packed as f32x2 pairs over heads (0,1) and (2,3): FFMA2 hot loop.
// ---------------------------------------------------------------------------
__global__ __launch_bounds__(128) void attn_kernel() {
    __shared__ float4 Vs[32*32];      // 16KB: [jj][d] -> float4 over heads
    __shared__ float4 Ps[4*8*32];     // 16KB: [warp][r][jj] -> float4 over heads

    int tid = threadIdx.x;
    int w = tid >> 5, lane = tid & 31;
    int row0 = blockIdx.x * 32;       // global row base (0..4095)
    int jh = blockIdx.y;              // j half
    int b = row0 >> 11;
    int rwbase = row0 + w * 8;        // this warp's global row base
    int i0 = rwbase & 2047;           // within-batch i base

    float4 eir[8];
    #pragma unroll
    for (int r = 0; r < 8; r++)
        eir[r] = *(const float4*)(g_EI + (size_t)(rwbase + r)*4);

    unsigned long long acc01[8], acc23[8];
    float sp[8][4];
    #pragma unroll
    for (int r = 0; r < 8; r++) {
        acc01[r] = 0ull; acc23[r] = 0ull;
        #pragma unroll
        for (int h = 0; h < 4; h++) sp[r][h] = 0.f;
    }

    unsigned vs_base = (unsigned)__cvta_generic_to_shared(Vs);
    unsigned ps_warp = (unsigned)__cvta_generic_to_shared(Ps) + (unsigned)(w << 12);
    const float4* Vg  = (const float4*)g_V + (size_t)b*2048*32;
    const float4* EJg = (const float4*)g_EJ + b*2048;

    for (int jc = jh*32; jc < jh*32 + 32; ++jc) {
        int j0 = jc << 5;
        __syncthreads();
        {   // stage V chunk: 32 j x 32 d x 4 h = 1024 float4, 128 threads
            const float4* src = Vg + (size_t)j0*32;
            #pragma unroll
            for (int u = 0; u < 8; u++) Vs[tid + u*128] = src[tid + u*128];
        }
        __syncthreads();

        // p = exp(leaky(ei+ej)) * mask   (lane owns j = j0+lane)
        float4 ej4 = EJg[j0 + lane];
        float ejh[4] = {ej4.x, ej4.y, ej4.z, ej4.w};
        #pragma unroll
        for (int r = 0; r < 8; r++) {
            unsigned wrd = g_adjbits[(i0 + r)*64 + jc];
            float keep = (float)((wrd >> lane) & 1u);
            float4 pv;
            float* pvp = &pv.x;
            const float* eip = &eir[r].x;
            #pragma unroll
            for (int h = 0; h < 4; h++) {
                float tt = eip[h] + ejh[h];
                float lk = tt > 0.f ? tt : 0.2f * tt;
                float p = __expf(lk) * keep;
                sp[r][h] += p;
                pvp[h] = p;
            }
            Ps[w*256 + r*32 + lane] = pv;
        }
        __syncwarp();

        // AV accumulate: acc[h][d] += p[j][h] * V[j][d][h]  via f32x2
        #pragma unroll
        for (int jj = 0; jj < 32; jj++) {
            unsigned vaddr = vs_base + (((jj << 5) + lane) << 4);
            unsigned long long v01, v23;
            asm volatile("ld.shared.v2.u64 {%0,%1},[%2];"
                         : "=l"(v01), "=l"(v23) : "r"(vaddr));
            #pragma unroll
            for (int r = 0; r < 8; r++) {
                unsigned paddr = ps_warp + (((r << 5) + jj) << 4);
                unsigned long long p01, p23;
                asm volatile("ld.shared.v2.u64 {%0,%1},[%2];"
                             : "=l"(p01), "=l"(p23) : "r"(paddr));
                asm volatile("fma.rn.f32x2 %0,%1,%2,%0;"
                             : "+l"(acc01[r]) : "l"(p01), "l"(v01));
                asm volatile("fma.rn.f32x2 %0,%1,%2,%0;"
                             : "+l"(acc23[r]) : "l"(p23), "l"(v23));
            }
        }
    }

    // Write partial acc (un-normalized) + partial softmax sums
    #pragma unroll
    for (int r = 0; r < 8; r++) {
        float s0 = sp[r][0], s1 = sp[r][1], s2 = sp[r][2], s3 = sp[r][3];
        #pragma unroll
        for (int off = 16; off; off >>= 1) {
            s0 += __shfl_xor_sync(~0u, s0, off);
            s1 += __shfl_xor_sync(~0u, s1, off);
            s2 += __shfl_xor_sync(~0u, s2, off);
            s3 += __shfl_xor_sync(~0u, s3, off);
        }
        float a0, a1, a2, a3;
        asm("mov.b64 {%0,%1},%2;" : "=f"(a0), "=f"(a1) : "l"(acc01[r]));
        asm("mov.b64 {%0,%1},%2;" : "=f"(a2), "=f"(a3) : "l"(acc23[r]));
        size_t rowg = rwbase + r;
        float* prow = g_part + ((size_t)jh*4096 + rowg)*128;
        prow[lane]      = a0;
        prow[32 + lane] = a1;
        prow[64 + lane] = a2;
        prow[96 + lane] = a3;
        if (lane == 0) {
            float* srow = g_psum + ((size_t)jh*4096 + rowg)*4;
            srow[0] = s0; srow[1] = s1; srow[2] = s2; srow[3] = s3;
        }
    }
}

// ---------------------------------------------------------------------------
// Combine partials, residual, layernorm. 1 warp per row, 8 rows per block.
// ---------------------------------------------------------------------------
__global__ __launch_bounds__(256) void combine_kernel(const float* __restrict__ gamma,
                                                      const float* __restrict__ beta,
                                                      float* __restrict__ out) {
    int w = threadIdx.x >> 5, lane = threadIdx.x & 31;
    size_t row = (size_t)blockIdx.x * 8 + w;   // 0..4095

    const float* sa = g_psum + row*4;
    const float* sb = g_psum + (4096 + row)*4;
    float s0 = sa[0] + sb[0];
    float s1 = sa[1] + sb[1];
    float s2 = sa[2] + sb[2];
    float s3 = sa[3] + sb[3];

    const float* p0 = g_part + row*128;
    const float* p1 = g_part + (4096 + row)*128;
    const float* hrow = g_h + row*128;

    float y0 = (p0[lane]      + p1[lane])      / s0 + hrow[lane];
    float y1 = (p0[32 + lane] + p1[32 + lane]) / s1 + hrow[32 + lane];
    float y2 = (p0[64 + lane] + p1[64 + lane]) / s2 + hrow[64 + lane];
    float y3 = (p0[96 + lane] + p1[96 + lane]) / s3 + hrow[96 + lane];

    float ts = y0 + y1 + y2 + y3;
    #pragma unroll
    for (int off = 16; off; off >>= 1) ts += __shfl_xor_sync(~0u, ts, off);
    float mu = ts * (1.f/128.f);
    float d0 = y0 - mu, d1 = y1 - mu, d2 = y2 - mu, d3 = y3 - mu;
    float vs = d0*d0 + d1*d1 + d2*d2 + d3*d3;
    #pragma unroll
    for (int off = 16; off; off >>= 1) vs += __shfl_xor_sync(~0u, vs, off);
    float rs = rsqrtf(vs * (1.f/128.f) + EPSV);

    float* orow = out + row*128;
    orow[lane]      = d0 * rs * gamma[lane]      + beta[lane];
    orow[32 + lane] = d1 * rs * gamma[32 + lane] + beta[32 + lane];
    orow[64 + lane] = d2 * rs * gamma[64 + lane] + beta[64 + lane];
    orow[96 + lane] = d3 * rs * gamma[96 + lane] + beta[96 + lane];
}

extern "C" void kernel_launch(void* const* d_in, const int* in_sizes, int n_in,
                              void* d_out, int out_size) {
    const float* x     = (const float*)d_in[0];
    const int*   adj   = (const int*)  d_in[1];
    const float* w     = (const float*)d_in[2];
    const float* a     = (const float*)d_in[3];
    const float* gamma = (const float*)d_in[4];
    const float* beta  = (const float*)d_in[5];
    float* out = (float*)d_out;

    prep_kernel<<<256, 256>>>(x, w, a);
    adjbits_kernel<<<2048, 256>>>(adj);
    attn_kernel<<<dim3(128, 2), 128>>>();
    combine_kernel<<<512, 256>>>(gamma, beta, out);
}

// round 4
// speedup vs baseline: 1.4515x; 1.4515x over previous
#include <cuda_runtime.h>
#include <cstdint>

#define NB 2
#define NN 2048
#define NH 4
#define ND 32
#define NF 128
#define EPSV 1e-5f
#define NSPLIT 4

// Scratch (device globals — no allocation allowed)
__device__ float g_h[NB*NN*NF];                 // h = x @ w^T   [b][n][o]
__device__ float g_V[NB*NN*NF];                 // permuted V    [b][j][d][h]
__device__ float g_EI[NB*NN*NH];                // ei per (b,n,h)
__device__ float g_EJ[NB*NN*NH];                // ej per (b,n,h)
__device__ unsigned g_adjbits[NN*(NN/32)];      // adj bitmask [i][jword]
__device__ float g_part[NSPLIT*NB*NN*NF];       // partial AV   [js][row][o]
__device__ float g_psum[NSPLIT*NB*NN*NH];       // partial softmax sums [js][row][h]

// ---------------------------------------------------------------------------
// Prep: h = x@w^T, ei/ej, and the scrambled V gather ([b][j][d][h] layout)
// 16 rows per block, 256 threads.
// ---------------------------------------------------------------------------
__global__ __launch_bounds__(256) void prep_kernel(const float* __restrict__ x,
                                                   const float* __restrict__ w,
                                                   const float* __restrict__ a) {
    __shared__ float w_s[64*129];   // [k][o] padded stride 129 (conflict-free)
    __shared__ float x_s[16*64];
    __shared__ float h_s[16*128];
    __shared__ float a_s[NH*64];
    int t = threadIdx.x;
    int n0 = blockIdx.x * 16;       // global row base over B*N = 4096

    for (int idx = t; idx < 128*64; idx += 256) {
        int o = idx >> 6, k = idx & 63;
        w_s[k*129 + o] = w[idx];
    }
    for (int idx = t; idx < 16*64; idx += 256) x_s[idx] = x[n0*64 + idx];
    if (t < NH*64) a_s[t] = a[t];
    __syncthreads();

    {   // GEMM: thread computes 8 outputs for one row
        int r = t >> 4, og = t & 15;
        float acc[8];
        #pragma unroll
        for (int u = 0; u < 8; u++) acc[u] = 0.f;
        #pragma unroll
        for (int k = 0; k < 64; k++) {
            float xv = x_s[r*64 + k];
            #pragma unroll
            for (int u = 0; u < 8; u++)
                acc[u] = fmaf(xv, w_s[k*129 + og + u*16], acc[u]);
        }
        #pragma unroll
        for (int u = 0; u < 8; u++) {
            int o = og + u*16;
            h_s[r*128 + o] = acc[u];
            g_h[(size_t)(n0 + r)*128 + o] = acc[u];
        }
    }
    __syncthreads();

    // ei / ej
    if (t < 64) {
        int r = t >> 2, hh = t & 3;
        float ei = 0.f, ej = 0.f;
        #pragma unroll
        for (int d = 0; d < 32; d++) {
            float hv = h_s[r*128 + hh*32 + d];
            ei = fmaf(hv, a_s[hh*64 + d], ei);
            ej = fmaf(hv, a_s[hh*64 + 32 + d], ej);
        }
        int ng = n0 + r;
        g_EI[ng*4 + hh] = ei;
        g_EJ[ng*4 + hh] = ej;
    }
    // V scatter: v[b, g>>2, g&3, d] = h[b, n, ho, d] with g = ho*2048 + n
    {
        int r = t >> 4, dd = (t & 15) * 2;
        int ng = n0 + r;
        int b = ng >> 11, n = ng & 2047;
        #pragma unroll
        for (int ho = 0; ho < 4; ho++) {
            int g = ho*2048 + n;
            int j = g >> 2, hn = g & 3;
            int base = (b*2048 + j)*128 + hn;
            g_V[base + dd*4]       = h_s[r*128 + ho*32 + dd];
            g_V[base + (dd+1)*4]   = h_s[r*128 + ho*32 + dd + 1];
        }
    }
}

// ---------------------------------------------------------------------------
// adj -> bitmask (512 KB, L2 resident)
// ---------------------------------------------------------------------------
__global__ __launch_bounds__(256) void adjbits_kernel(const int* __restrict__ adj) {
    int w = threadIdx.x >> 5, lane = threadIdx.x & 31;
    int warp_g = blockIdx.x * 8 + w;
    #pragma unroll
    for (int u = 0; u < 8; u++) {
        int wi = warp_g * 8 + u;           // 0..131071
        int i = wi >> 6, c = wi & 63;
        int v = adj[(size_t)i*2048 + c*32 + lane];
        unsigned m = __ballot_sync(0xFFFFFFFFu, v != 0);
        if (lane == 0) g_adjbits[wi] = m;
    }
}

// ---------------------------------------------------------------------------
// Main attention (partial over a quarter of the j-range).
// Grid (128, 4): blockIdx.x = 32-row tile over B*N rows, blockIdx.y = j quarter.
// 128 threads = 4 warps, 4 CTAs/SM; warp handles 8 i-rows; lane = d.
// acc packed as f32x2 pairs over heads (0,1) and (2,3): FFMA2 hot loop.
// ---------------------------------------------------------------------------
__global__ __launch_bounds__(128, 4) void attn_kernel() {
    __shared__ float4 Vs[32*32];      // 16KB: [jj][d] -> float4 over heads
    __shared__ float4 Ps[4*8*32];     // 16KB: [warp][r][jj] -> float4 over heads

    int tid = threadIdx.x;
    int w = tid >> 5, lane = tid & 31;
    int row0 = blockIdx.x * 32;       // global row base (0..4095)
    int jh = blockIdx.y;              // j quarter (0..3)
    int b = row0 >> 11;
    int rwbase = row0 + w * 8;        // this warp's global row base
    int i0 = rwbase & 2047;           // within-batch i base

    unsigned long long acc01[8], acc23[8];
    float sp[8][4];
    #pragma unroll
    for (int r = 0; r < 8; r++) {
        acc01[r] = 0ull; acc23[r] = 0ull;
        #pragma unroll
        for (int h = 0; h < 4; h++) sp[r][h] = 0.f;
    }

    unsigned vs_base = (unsigned)__cvta_generic_to_shared(Vs);
    unsigned ps_warp = (unsigned)__cvta_generic_to_shared(Ps) + (unsigned)(w << 12);
    const float4* Vg  = (const float4*)g_V + (size_t)b*2048*32;
    const float4* EJg = (const float4*)g_EJ + b*2048;
    const float4* EIg = (const float4*)g_EI;

    for (int jc = jh*16; jc < jh*16 + 16; ++jc) {
        int j0 = jc << 5;

        // Prefetch this chunk's per-row scalars BEFORE the barrier so their
        // L2 latency hides under sync + V staging.
        float4 ej4 = EJg[j0 + lane];
        unsigned wrd[8];
        float4 ei4[8];
        #pragma unroll
        for (int r = 0; r < 8; r++) {
            wrd[r] = g_adjbits[(i0 + r)*64 + jc];
            ei4[r] = EIg[rwbase + r];
        }

        __syncthreads();
        {   // stage V chunk: 32 j x 32 d x 4 h = 1024 float4, 128 threads
            const float4* src = Vg + (size_t)j0*32;
            #pragma unroll
            for (int u = 0; u < 8; u++) Vs[tid + u*128] = src[tid + u*128];
        }
        __syncthreads();

        // p = exp(leaky(ei+ej)) * mask   (lane owns j = j0+lane)
        float ejh[4] = {ej4.x, ej4.y, ej4.z, ej4.w};
        #pragma unroll
        for (int r = 0; r < 8; r++) {
            float keep = (float)((wrd[r] >> lane) & 1u);
            float4 pv;
            float* pvp = &pv.x;
            const float* eip = &ei4[r].x;
            #pragma unroll
            for (int h = 0; h < 4; h++) {
                float tt = eip[h] + ejh[h];
                float lk = tt > 0.f ? tt : 0.2f * tt;
                float p = __expf(lk) * keep;
                sp[r][h] += p;
                pvp[h] = p;
            }
            Ps[w*256 + r*32 + lane] = pv;
        }
        __syncwarp();

        // AV accumulate: acc[h][d] += p[j][h] * V[j][d][h]  via f32x2
        #pragma unroll
        for (int jj = 0; jj < 32; jj++) {
            unsigned vaddr = vs_base + (((jj << 5) + lane) << 4);
            unsigned long long v01, v23;
            asm volatile("ld.shared.v2.u64 {%0,%1},[%2];"
                         : "=l"(v01), "=l"(v23) : "r"(vaddr));
            #pragma unroll
            for (int r = 0; r < 8; r++) {
                unsigned paddr = ps_warp + (((r << 5) + jj) << 4);
                unsigned long long p01, p23;
                asm volatile("ld.shared.v2.u64 {%0,%1},[%2];"
                             : "=l"(p01), "=l"(p23) : "r"(paddr));
                asm volatile("fma.rn.f32x2 %0,%1,%2,%0;"
                             : "+l"(acc01[r]) : "l"(p01), "l"(v01));
                asm volatile("fma.rn.f32x2 %0,%1,%2,%0;"
                             : "+l"(acc23[r]) : "l"(p23), "l"(v23));
            }
        }
    }

    // Write partial acc (un-normalized) + partial softmax sums
    #pragma unroll
    for (int r = 0; r < 8; r++) {
        float s0 = sp[r][0], s1 = sp[r][1], s2 = sp[r][2], s3 = sp[r][3];
        #pragma unroll
        for (int off = 16; off; off >>= 1) {
            s0 += __shfl_xor_sync(~0u, s0, off);
            s1 += __shfl_xor_sync(~0u, s1, off);
            s2 += __shfl_xor_sync(~0u, s2, off);
            s3 += __shfl_xor_sync(~0u, s3, off);
        }
        float a0, a1, a2, a3;
        asm("mov.b64 {%0,%1},%2;" : "=f"(a0), "=f"(a1) : "l"(acc01[r]));
        asm("mov.b64 {%0,%1},%2;" : "=f"(a2), "=f"(a3) : "l"(acc23[r]));
        size_t rowg = rwbase + r;
        float* prow = g_part + ((size_t)jh*4096 + rowg)*128;
        prow[lane]      = a0;
        prow[32 + lane] = a1;
        prow[64 + lane] = a2;
        prow[96 + lane] = a3;
        if (lane == 0) {
            float* srow = g_psum + ((size_t)jh*4096 + rowg)*4;
            srow[0] = s0; srow[1] = s1; srow[2] = s2; srow[3] = s3;
        }
    }
}

// ---------------------------------------------------------------------------
// Combine partials, residual, layernorm. 1 warp per row, 8 rows per block.
// ---------------------------------------------------------------------------
__global__ __launch_bounds__(256) void combine_kernel(const float* __restrict__ gamma,
                                                      const float* __restrict__ beta,
                                                      float* __restrict__ out) {
    int w = threadIdx.x >> 5, lane = threadIdx.x & 31;
    size_t row = (size_t)blockIdx.x * 8 + w;   // 0..4095

    float s0 = 0.f, s1 = 0.f, s2 = 0.f, s3 = 0.f;
    float y0 = 0.f, y1 = 0.f, y2 = 0.f, y3 = 0.f;
    #pragma unroll
    for (int js = 0; js < NSPLIT; js++) {
        const float* srow = g_psum + ((size_t)js*4096 + row)*4;
        s0 += srow[0]; s1 += srow[1]; s2 += srow[2]; s3 += srow[3];
        const float* prow = g_part + ((size_t)js*4096 + row)*128;
        y0 += prow[lane];
        y1 += prow[32 + lane];
        y2 += prow[64 + lane];
        y3 += prow[96 + lane];
    }

    const float* hrow = g_h + row*128;
    y0 = y0 / s0 + hrow[lane];
    y1 = y1 / s1 + hrow[32 + lane];
    y2 = y2 / s2 + hrow[64 + lane];
    y3 = y3 / s3 + hrow[96 + lane];

    float ts = y0 + y1 + y2 + y3;
    #pragma unroll
    for (int off = 16; off; off >>= 1) ts += __shfl_xor_sync(~0u, ts, off);
    float mu = ts * (1.f/128.f);
    float d0 = y0 - mu, d1 = y1 - mu, d2 = y2 - mu, d3 = y3 - mu;
    float vs = d0*d0 + d1*d1 + d2*d2 + d3*d3;
    #pragma unroll
    for (int off = 16; off; off >>= 1) vs += __shfl_xor_sync(~0u, vs, off);
    float rs = rsqrtf(vs * (1.f/128.f) + EPSV);

    float* orow = out + row*128;
    orow[lane]      = d0 * rs * gamma[lane]      + beta[lane];
    orow[32 + lane] = d1 * rs * gamma[32 + lane] + beta[32 + lane];
    orow[64 + lane] = d2 * rs * gamma[64 + lane] + beta[64 + lane];
    orow[96 + lane] = d3 * rs * gamma[96 + lane] + beta[96 + lane];
}

extern "C" void kernel_launch(void* const* d_in, const int* in_sizes, int n_in,
                              void* d_out, int out_size) {
    const float* x     = (const float*)d_in[0];
    const int*   adj   = (const int*)  d_in[1];
    const float* w     = (const float*)d_in[2];
    const float* a     = (const float*)d_in[3];
    const float* gamma = (const float*)d_in[4];
    const float* beta  = (const float*)d_in[5];
    float* out = (float*)d_out;

    prep_kernel<<<256, 256>>>(x, w, a);
    adjbits_kernel<<<2048, 256>>>(adj);
    attn_kernel<<<dim3(128, NSPLIT), 128>>>();
    combine_kernel<<<512, 256>>>(gamma, beta, out);
}